// round 9
// baseline (speedup 1.0000x reference)
#include <cuda_runtime.h>

#define NTHREADS 256
#define GRID_BLOCKS (148 * 16)

// Zero-initialized accumulators; the last block resets them after reading,
// so every graph replay starts from zero.
__device__ double g_iou_sum;
__device__ double g_valid_cnt;
// Completion counter; atomicInc wraps to 0 at gridDim -> self-resetting.
__device__ unsigned int g_count;

__global__ void __launch_bounds__(NTHREADS)
iou_reduce_kernel(const float4* __restrict__ pred,
                  const float4* __restrict__ truth,
                  int n, float* __restrict__ out, int out_size) {
    float lsum = 0.0f;
    float lcnt = 0.0f;

    int idx = blockIdx.x * NTHREADS + threadIdx.x;
    int stride = gridDim.x * NTHREADS;

    // Natural (non-unrolled) grid-stride loop: low MLP_p1 keeps cross-CTA
    // L1tex-queue contention / CTA spread low (R8-measured 6.4 TB/s).
    for (int i = idx; i < n; i += stride) {
        float4 p = __ldg(pred + i);
        float4 t = __ldg(truth + i);

        float phw = p.z * 0.5f, phh = p.w * 0.5f;
        float thw = t.z * 0.5f, thh = t.w * 0.5f;

        float ix = fminf(p.x + phw, t.x + thw) - fmaxf(p.x - phw, t.x - thw);
        float iy = fminf(p.y + phh, t.y + thh) - fmaxf(p.y - phh, t.y - thh);
        float inter = fmaxf(ix, 0.0f) * fmaxf(iy, 0.0f);

        float area_p = p.z * p.w;      // valid boxes have w,h >= 0
        float area_t = t.z * t.w;
        float iou = inter / (area_p + area_t - inter + 1e-6f);

        bool valid = !(t.z == -1.0f && t.w == -1.0f);  // sentinel [-1]*4
        if (valid) {
            lsum += iou;
            lcnt += 1.0f;
        }
    }

    // Warp reduce
    #pragma unroll
    for (int off = 16; off > 0; off >>= 1) {
        lsum += __shfl_down_sync(0xffffffffu, lsum, off);
        lcnt += __shfl_down_sync(0xffffffffu, lcnt, off);
    }

    __shared__ float ssum[NTHREADS / 32];
    __shared__ float scnt[NTHREADS / 32];
    int warp = threadIdx.x >> 5;
    int lane = threadIdx.x & 31;
    if (lane == 0) {
        ssum[warp] = lsum;
        scnt[warp] = lcnt;
    }
    __syncthreads();

    __shared__ bool is_last;
    if (threadIdx.x == 0) {
        float bsum = 0.0f, bcnt = 0.0f;
        #pragma unroll
        for (int w = 0; w < NTHREADS / 32; w++) {
            bsum += ssum[w];
            bcnt += scnt[w];
        }
        atomicAdd(&g_iou_sum, (double)bsum);
        atomicAdd(&g_valid_cnt, (double)bcnt);
        __threadfence();
        unsigned int old = atomicInc(&g_count, gridDim.x - 1);
        is_last = (old == gridDim.x - 1);   // wraps to 0 -> self-resetting
    }
    __syncthreads();

    if (is_last && threadIdx.x == 0) {
        // All blocks' atomicAdds precede their atomicInc (fenced), so the
        // totals are complete here.
        double s = g_iou_sum;
        double c = g_valid_cnt;
        float m = (c > 0.0) ? (float)(s / (c < 1.0 ? 1.0 : c)) : 0.0f;
        for (int i = 0; i < out_size; i++) out[i] = m;
        g_iou_sum = 0.0;        // deferred reset for the next replay
        g_valid_cnt = 0.0;
    }
}

extern "C" void kernel_launch(void* const* d_in, const int* in_sizes, int n_in,
                              void* d_out, int out_size) {
    const float4* pred  = (const float4*)d_in[0];
    const float4* truth = (const float4*)d_in[1];
    int n = in_sizes[0] / 4;   // number of boxes (float4 elements)

    int blocks = GRID_BLOCKS;
    int needed = (n + NTHREADS - 1) / NTHREADS;
    if (blocks > needed) blocks = needed;

    iou_reduce_kernel<<<blocks, NTHREADS>>>(pred, truth, n,
                                            (float*)d_out, out_size);
}

// round 10
// speedup vs baseline: 1.0098x; 1.0098x over previous
#include <cuda_runtime.h>

#define NTHREADS 256
#define GRID_BLOCKS (148 * 16)

// Zero-initialized accumulators; the last block resets them after reading,
// so every graph replay starts from zero.
__device__ double g_iou_sum;
__device__ double g_valid_cnt;
// Completion counter; atomicInc wraps to 0 at gridDim -> self-resetting.
__device__ unsigned int g_count;

// Read-only vectorized load with 256B L2 fetch granularity: halves the number
// of DRAM requests for this perfectly-sequential stream.
__device__ __forceinline__ float4 ldg_nc_256(const float4* p) {
    float4 v;
    asm("ld.global.nc.L2::256B.v4.f32 {%0, %1, %2, %3}, [%4];"
        : "=f"(v.x), "=f"(v.y), "=f"(v.z), "=f"(v.w)
        : "l"(p));
    return v;
}

__global__ void __launch_bounds__(NTHREADS)
iou_reduce_kernel(const float4* __restrict__ pred,
                  const float4* __restrict__ truth,
                  int n, float* __restrict__ out, int out_size) {
    float lsum = 0.0f;
    float lcnt = 0.0f;

    int idx = blockIdx.x * NTHREADS + threadIdx.x;
    int stride = gridDim.x * NTHREADS;

    // Natural (non-unrolled) grid-stride loop: low MLP_p1 measured fastest
    // (R9: 35.4us vs 38.3-38.9us for unrolled variants).
    for (int i = idx; i < n; i += stride) {
        float4 p = ldg_nc_256(pred + i);
        float4 t = ldg_nc_256(truth + i);

        float phw = p.z * 0.5f, phh = p.w * 0.5f;
        float thw = t.z * 0.5f, thh = t.w * 0.5f;

        float ix = fminf(p.x + phw, t.x + thw) - fmaxf(p.x - phw, t.x - thw);
        float iy = fminf(p.y + phh, t.y + thh) - fmaxf(p.y - phh, t.y - thh);
        float inter = fmaxf(ix, 0.0f) * fmaxf(iy, 0.0f);

        float area_p = p.z * p.w;      // valid boxes have w,h >= 0
        float area_t = t.z * t.w;
        float iou = inter / (area_p + area_t - inter + 1e-6f);

        bool valid = !(t.z == -1.0f && t.w == -1.0f);  // sentinel [-1]*4
        if (valid) {
            lsum += iou;
            lcnt += 1.0f;
        }
    }

    // Warp reduce
    #pragma unroll
    for (int off = 16; off > 0; off >>= 1) {
        lsum += __shfl_down_sync(0xffffffffu, lsum, off);
        lcnt += __shfl_down_sync(0xffffffffu, lcnt, off);
    }

    __shared__ float ssum[NTHREADS / 32];
    __shared__ float scnt[NTHREADS / 32];
    int warp = threadIdx.x >> 5;
    int lane = threadIdx.x & 31;
    if (lane == 0) {
        ssum[warp] = lsum;
        scnt[warp] = lcnt;
    }
    __syncthreads();

    __shared__ bool is_last;
    if (threadIdx.x == 0) {
        float bsum = 0.0f, bcnt = 0.0f;
        #pragma unroll
        for (int w = 0; w < NTHREADS / 32; w++) {
            bsum += ssum[w];
            bcnt += scnt[w];
        }
        atomicAdd(&g_iou_sum, (double)bsum);
        atomicAdd(&g_valid_cnt, (double)bcnt);
        __threadfence();
        unsigned int old = atomicInc(&g_count, gridDim.x - 1);
        is_last = (old == gridDim.x - 1);   // wraps to 0 -> self-resetting
    }
    __syncthreads();

    if (is_last && threadIdx.x == 0) {
        double s = g_iou_sum;
        double c = g_valid_cnt;
        float m = (c > 0.0) ? (float)(s / (c < 1.0 ? 1.0 : c)) : 0.0f;
        for (int i = 0; i < out_size; i++) out[i] = m;
        g_iou_sum = 0.0;        // deferred reset for the next replay
        g_valid_cnt = 0.0;
    }
}

extern "C" void kernel_launch(void* const* d_in, const int* in_sizes, int n_in,
                              void* d_out, int out_size) {
    const float4* pred  = (const float4*)d_in[0];
    const float4* truth = (const float4*)d_in[1];
    int n = in_sizes[0] / 4;   // number of boxes (float4 elements)

    int blocks = GRID_BLOCKS;
    int needed = (n + NTHREADS - 1) / NTHREADS;
    if (blocks > needed) blocks = needed;

    iou_reduce_kernel<<<blocks, NTHREADS>>>(pred, truth, n,
                                            (float*)d_out, out_size);
}